// round 4
// baseline (speedup 1.0000x reference)
#include <cuda_runtime.h>

#define BB 16
#define SS 2048
#define NC 8
#define NT 256
#define RPB 8                    // blocks per row
#define GRIDN (BB * RPB)         // 128 blocks, all co-resident on 148 SMs
#define LOG2E 1.4426950408889634f
#define T1V 100.0f
#define EPSV 1e-8f

__device__ __forceinline__ float ex2(float x) {
    float y; asm("ex2.approx.ftz.f32 %0, %1;" : "=f"(y) : "f"(x)); return y;
}
__device__ __forceinline__ float flog(float x) {
    float y; asm("lg2.approx.ftz.f32 %0, %1;" : "=f"(y) : "f"(x));
    return y * 0.6931471805599453f;
}

// Cross-block state (no allocs allowed). All reset/regenerated every run.
__device__ float        g_aggV[GRIDN][NC];   // per-block class aggregates
__device__ float        g_aggT[GRIDN];       // per-block anchor timestamps
__device__ double       g_partials[GRIDN];
__device__ unsigned     g_count;             // grid-barrier arrivals (reset each run)
__device__ volatile unsigned g_sense;        // grid-barrier generation (monotonic)
__device__ unsigned     g_ticket;            // finalization ticket (reset each run)

__global__ __launch_bounds__(NT)
void hawkes_kernel(const float* __restrict__ ts,
                   const int*   __restrict__ ms,
                   const float* __restrict__ mu,
                   const float* __restrict__ alphas,
                   const float* __restrict__ beta,
                   float*       __restrict__ out)
{
    __shared__ float AB[NC * NC];      // alphas[m][c] * beta[c]
    __shared__ float colsum[NC];       // sum_k alphas[k][c]
    __shared__ float mu_s[NC];
    __shared__ float beta_s[NC];
    __shared__ float Wagg[NC][NC + 1]; // per-warp aggregates   [warp][class]
    __shared__ float WT[NC];           // per-warp anchor times
    __shared__ float inclW[NC][NC + 1];// inclusive warp-prefix  [warp][class]
    __shared__ float bpV[NC];          // block-exclusive prefix for this block
    __shared__ float bpT[1];
    __shared__ double wsum[NC];

    const int bx   = blockIdx.x;
    const int row  = bx >> 3;          // / RPB
    const int blk  = bx & (RPB - 1);
    const int t    = threadIdx.x;
    const int w    = t >> 5;
    const int lane = t & 31;

    // ---- Parameter staging ----
    if (t < NC * NC) AB[t] = alphas[t] * beta[t & (NC - 1)];
    if (t < NC) {
        float s = 0.f;
        #pragma unroll
        for (int k = 0; k < NC; k++) s += alphas[k * NC + t];
        colsum[t] = s;
        mu_s[t]   = mu[t];
        beta_s[t] = beta[t];
    }
    __syncthreads();
    float bl2[NC];
    #pragma unroll
    for (int c = 0; c < NC; c++) bl2[c] = beta_s[c] * LOG2E;

    // ---- Load this thread's single event (coalesced LDG.32) ----
    const int   gi    = row * SS + blk * NT + t;
    const float ti    = ts[gi];
    const int   m     = ms[gi];
    const bool  valid = (ti > 0.f);

    // One-hot element anchored at own timestamp: V_c = [c==m && valid] (value e^0 = 1)
    float V[NC];
    #pragma unroll
    for (int c = 0; c < NC; c++) V[c] = 0.f;
    if (valid) V[m] = 1.f;

    // ---- Warp-level inclusive Kogge-Stone scan (registers, shfl) ----
    #pragma unroll
    for (int off = 1; off < 32; off <<= 1) {
        float Tp = __shfl_up_sync(0xffffffffu, ti, off);
        float Vp[NC];
        #pragma unroll
        for (int c = 0; c < NC; c++) Vp[c] = __shfl_up_sync(0xffffffffu, V[c], off);
        if (lane >= off) {
            #pragma unroll
            for (int c = 0; c < NC; c++)
                V[c] += Vp[c] * ex2(bl2[c] * (Tp - ti));   // Tp <= ti (sorted)
        }
    }

    // ---- Publish per-warp aggregates (lane 31 holds warp-inclusive total) ----
    if (lane == 31) {
        #pragma unroll
        for (int c = 0; c < NC; c++) Wagg[w][c] = V[c];
        WT[w] = ti;
    }
    __syncthreads();

    // ---- Serial inclusive scan over the 8 warps (thread c handles class c) ----
    if (t < NC) {
        const int c = t;
        float run = 0.f, Tprev = WT[0];
        #pragma unroll
        for (int ww = 0; ww < NC; ww++) {
            float Tw = WT[ww];
            run = Wagg[ww][c] + run * ex2(bl2[c] * (Tprev - Tw));
            inclW[ww][c] = run;
            Tprev = Tw;
        }
        // Block-inclusive aggregate = inclW[7], anchored at WT[7]. Publish.
        g_aggV[bx][c] = run;
        if (c == 0) g_aggT[bx] = WT[NC - 1];
    }
    __syncthreads();

    // ---- Apply exclusive warp-prefix to each thread ----
    if (w > 0) {
        const float Tp = WT[w - 1];
        #pragma unroll
        for (int c = 0; c < NC; c++)
            V[c] += inclW[w - 1][c] * ex2(bl2[c] * (Tp - ti));
    }

    // ---- Grid barrier (sense-reversal; replay-safe: count resets, sense monotonic) ----
    if (t == 0) {
        __threadfence();
        unsigned gen = g_sense;
        unsigned arrived = atomicAdd(&g_count, 1u);
        if (arrived == GRIDN - 1) {
            g_count = 0;
            __threadfence();
            g_sense = gen + 1;
        } else {
            while (g_sense == gen) { __nanosleep(64); }
        }
        __threadfence();
    }
    __syncthreads();

    // ---- Block-exclusive prefix over previous blocks of this row ----
    if (t < NC) {
        const int c = t;
        float pV = 0.f, pT = 0.f;
        for (int bk = 0; bk < blk; bk++) {
            const int idx = row * RPB + bk;
            float Tb = __ldcg(&g_aggT[idx]);
            pV = __ldcg(&g_aggV[idx][c]) + pV * ex2(bl2[c] * (pT - Tb));
            pT = Tb;
        }
        bpV[c] = pV;
        if (c == 0) bpT[0] = pT;
    }
    __syncthreads();

    if (blk > 0) {
        const float Tp = bpT[0];
        #pragma unroll
        for (int c = 0; c < NC; c++)
            V[c] += bpV[c] * ex2(bl2[c] * (Tp - ti));
    }

    // ---- Per-event log-likelihood term ----
    double acc = 0.0;
    if (valid) {
        V[m] -= 1.f;                         // exclude own event (j < i strict)
        float lam = mu_s[m];
        #pragma unroll
        for (int c = 0; c < NC; c++) lam += AB[m * NC + c] * V[c];
        float contrib = flog(lam + EPSV)
                      - colsum[m] * (1.f - ex2(-bl2[m] * (T1V - ti)));
        acc = (double)contrib;
    }

    // ---- Reductions: warp shfl -> block -> global (fixed order, deterministic) ----
    #pragma unroll
    for (int off = 16; off > 0; off >>= 1)
        acc += __shfl_down_sync(0xffffffffu, acc, off);
    if (lane == 0) wsum[w] = acc;
    __syncthreads();

    if (t == 0) {
        double s = 0.0;
        #pragma unroll
        for (int ww = 0; ww < NC; ww++) s += wsum[ww];
        g_partials[bx] = s;
        __threadfence();
        unsigned tk = atomicAdd(&g_ticket, 1u);
        if (tk == GRIDN - 1) {               // last block finalizes (fixed-order sum)
            __threadfence();
            double tot = 0.0;
            #pragma unroll
            for (int i = 0; i < GRIDN; i++) tot += __ldcg(&g_partials[i]);
            double musum = 0.0;
            #pragma unroll
            for (int c = 0; c < NC; c++) musum += (double)mu_s[c];
            out[0] = (float)(tot - musum * (double)T1V);
            __threadfence();
            g_ticket = 0;                    // reset for next graph replay
        }
    }
}

extern "C" void kernel_launch(void* const* d_in, const int* in_sizes, int n_in,
                              void* d_out, int out_size)
{
    const float* ts     = (const float*)d_in[0];
    const int*   ms     = (const int*)  d_in[1];
    const float* mu     = (const float*)d_in[2];
    const float* alphas = (const float*)d_in[3];
    const float* beta   = (const float*)d_in[4];
    float*       out    = (float*)d_out;

    hawkes_kernel<<<GRIDN, NT>>>(ts, ms, mu, alphas, beta, out);
}

// round 5
// speedup vs baseline: 1.2743x; 1.2743x over previous
#include <cuda_runtime.h>

#define BB 16
#define SS 2048
#define NC 8
#define NT 512
#define NW (NT / 32)           // 16 warps
#define CHUNK 4                // SS / NT
#define LOG2E 1.4426950408889634f
#define T1V 100.0f
#define EPSV 1e-8f

__device__ __forceinline__ float ex2(float x) {
    float y; asm("ex2.approx.ftz.f32 %0, %1;" : "=f"(y) : "f"(x)); return y;
}
__device__ __forceinline__ float flog(float x) {
    float y; asm("lg2.approx.ftz.f32 %0, %1;" : "=f"(y) : "f"(x));
    return y * 0.6931471805599453f;
}

// Cross-block state (no allocations allowed). Replay-safe.
__device__ double   g_partials[BB];
__device__ unsigned g_ticket;          // last block resets to 0 each run

__global__ __launch_bounds__(NT)
void hawkes_kernel(const float* __restrict__ ts,
                   const int*   __restrict__ ms,
                   const float* __restrict__ mu,
                   const float* __restrict__ alphas,
                   const float* __restrict__ beta,
                   float*       __restrict__ out)
{
    __shared__ float  AB[NC * NC];       // alphas[m][c] * beta[c]
    __shared__ float  colsum[NC];        // sum_k alphas[k][c]
    __shared__ float  mu_s[NC];
    __shared__ float  beta_s[NC];
    __shared__ float  Wagg[NW][NC + 1];  // per-warp chunk-scan totals
    __shared__ float  WT[NW];            // per-warp anchor timestamps
    __shared__ float  inclW[NW][NC + 1]; // inclusive warp-level prefix
    __shared__ double wsum[NW];

    const int b    = blockIdx.x;         // one block per batch row
    const int t    = threadIdx.x;
    const int w    = t >> 5;
    const int lane = t & 31;

    // ---- Parameter staging ----
    if (t < NC * NC) AB[t] = alphas[t] * beta[t & (NC - 1)];
    if (t < NC) {
        float s = 0.f;
        #pragma unroll
        for (int k = 0; k < NC; k++) s += alphas[k * NC + t];
        colsum[t] = s;
        mu_s[t]   = mu[t];
        beta_s[t] = beta[t];
    }
    __syncthreads();
    float bl2[NC];
    #pragma unroll
    for (int c = 0; c < NC; c++) bl2[c] = beta_s[c] * LOG2E;

    // ---- Load this thread's 4 events directly (LDG.128, coalesced) ----
    float tloc[CHUNK];
    int   mloc[CHUNK];
    *(float4*)tloc = ((const float4*)(ts + b * SS))[t];
    *(int4*)mloc   = ((const int4*)  (ms + b * SS))[t];

    // ---- Phase 1: chunk aggregate anchored at chunk's last timestamp ----
    const float Tt = tloc[CHUNK - 1];
    float V[NC];
    #pragma unroll
    for (int c = 0; c < NC; c++) V[c] = 0.f;
    #pragma unroll
    for (int j = 0; j < CHUNK; j++) {
        float tj = tloc[j];
        int   m  = mloc[j];
        if (tj > 0.f) V[m] += ex2(bl2[m] * (tj - Tt));  // exponent <= 0
    }

    // ---- Warp-level inclusive Kogge-Stone over chunk aggregates (shfl) ----
    #pragma unroll
    for (int off = 1; off < 32; off <<= 1) {
        float Tp = __shfl_up_sync(0xffffffffu, Tt, off);
        float Vp[NC];
        #pragma unroll
        for (int c = 0; c < NC; c++) Vp[c] = __shfl_up_sync(0xffffffffu, V[c], off);
        if (lane >= off) {
            #pragma unroll
            for (int c = 0; c < NC; c++)
                V[c] += Vp[c] * ex2(bl2[c] * (Tp - Tt));   // Tp <= Tt (sorted)
        }
    }

    // ---- Publish per-warp totals ----
    if (lane == 31) {
        #pragma unroll
        for (int c = 0; c < NC; c++) Wagg[w][c] = V[c];
        WT[w] = Tt;
    }
    __syncthreads();

    // ---- Serial inclusive scan over 16 warps (thread c owns class c) ----
    if (t < NC) {
        const int c = t;
        float run = 0.f, Tprev = WT[0];
        #pragma unroll
        for (int ww = 0; ww < NW; ww++) {
            float Tw = WT[ww];
            run = Wagg[ww][c] + run * ex2(bl2[c] * (Tprev - Tw));
            inclW[ww][c] = run;
            Tprev = Tw;
        }
    }
    __syncthreads();

    // ---- Fold warp-exclusive prefix into each lane's inclusive value ----
    if (w > 0) {
        const float Tp = WT[w - 1];
        #pragma unroll
        for (int c = 0; c < NC; c++)
            V[c] += inclW[w - 1][c] * ex2(bl2[c] * (Tp - Tt));
    }

    // ---- Replay start state = previous lane's inclusive value ----
    float L[NC];
    float Tstart;
    #pragma unroll
    for (int c = 0; c < NC; c++) L[c] = __shfl_up_sync(0xffffffffu, V[c], 1);
    Tstart = __shfl_up_sync(0xffffffffu, Tt, 1);
    if (lane == 0) {
        if (w > 0) {
            #pragma unroll
            for (int c = 0; c < NC; c++) L[c] = inclW[w - 1][c];
            Tstart = WT[w - 1];
        } else {
            #pragma unroll
            for (int c = 0; c < NC; c++) L[c] = 0.f;
            Tstart = tloc[0];
        }
    }

    // ---- Phase 3: sequential replay of own 4 events ----
    double acc = 0.0;
    float tprev = Tstart;
    #pragma unroll
    for (int j = 0; j < CHUNK; j++) {
        const float ti = tloc[j];
        const int   m  = mloc[j];
        const float dt = ti - tprev;
        tprev = ti;

        float lam = mu_s[m];
        #pragma unroll
        for (int c = 0; c < NC; c++) {
            L[c] *= ex2(-bl2[c] * dt);
            lam  += AB[m * NC + c] * L[c];
        }
        if (ti > 0.f) {
            float contrib = flog(lam + EPSV)
                          - colsum[m] * (1.f - ex2(-bl2[m] * (T1V - ti)));
            acc += (double)contrib;
            L[m] += 1.f;
        }
    }

    // ---- Reductions: warp shfl -> block -> ticketed global finalize ----
    #pragma unroll
    for (int off = 16; off > 0; off >>= 1)
        acc += __shfl_down_sync(0xffffffffu, acc, off);
    if (lane == 0) wsum[w] = acc;
    __syncthreads();

    if (t == 0) {
        double s = 0.0;
        #pragma unroll
        for (int ww = 0; ww < NW; ww++) s += wsum[ww];
        g_partials[b] = s;
        __threadfence();
        unsigned tk = atomicAdd(&g_ticket, 1u);
        if (tk == BB - 1) {                  // last block finalizes, fixed order
            __threadfence();
            double tot = 0.0;
            #pragma unroll
            for (int i = 0; i < BB; i++) tot += __ldcg(&g_partials[i]);
            double musum = 0.0;
            #pragma unroll
            for (int c = 0; c < NC; c++) musum += (double)mu_s[c];
            out[0] = (float)(tot - musum * (double)T1V);
            __threadfence();
            g_ticket = 0;                    // reset for next graph replay
        }
    }
}

extern "C" void kernel_launch(void* const* d_in, const int* in_sizes, int n_in,
                              void* d_out, int out_size)
{
    const float* ts     = (const float*)d_in[0];
    const int*   ms     = (const int*)  d_in[1];
    const float* mu     = (const float*)d_in[2];
    const float* alphas = (const float*)d_in[3];
    const float* beta   = (const float*)d_in[4];
    float*       out    = (float*)d_out;

    hawkes_kernel<<<BB, NT>>>(ts, ms, mu, alphas, beta, out);
}